// round 1
// baseline (speedup 1.0000x reference)
#include <cuda_runtime.h>

#define NN   40000
#define EE   640000
#define FIN  512
#define HH   8
#define FO   32
#define CC   256          // HH * FO
#define NEG_SLOPE 0.2f
#define EPS  1e-16f

// ---------------- scratch (global device arrays; no allocation) ----------------
__device__ float g_h[NN * CC];        // projected features [N, H*F]
__device__ float g_B[FIN * CC];       // repacked W as [512, 256]
__device__ float g_ssrc[NN * HH];
__device__ float g_sdst[NN * HH];
__device__ int   g_cnt[NN];
__device__ int   g_ctr[NN];
__device__ int   g_off[NN + 1];
__device__ int   g_csrc[EE];          // src node id per CSR slot (sorted by dst)

// ---------------- pack W[H,512,32] -> B[512,256] ----------------
__global__ void packB_kernel(const float* __restrict__ W) {
    int idx = blockIdx.x * blockDim.x + threadIdx.x;
    if (idx < FIN * CC) {
        int d = idx >> 8;          // row (k)
        int c = idx & 255;         // col = head*32 + f
        g_B[idx] = W[(c >> 5) * (FIN * FO) + d * FO + (c & 31)];
    }
}

__global__ void zero_kernel() {
    int idx = blockIdx.x * blockDim.x + threadIdx.x;
    if (idx < NN) { g_cnt[idx] = 0; g_ctr[idx] = 0; }
}

// ---------------- SGEMM: g_h = x(40000x512) * g_B(512x256) ----------------
// 128x128 tile, BK=8, 256 threads, 8x8 per thread, double-buffered smem
__global__ __launch_bounds__(256, 2) void sgemm_kernel(const float* __restrict__ A) {
    __shared__ float As[2][8][128];
    __shared__ float Bs[2][8][128];

    int t   = threadIdx.x;
    int tx  = t & 15;
    int ty  = t >> 4;
    int bm0 = blockIdx.y * 128;
    int bc0 = blockIdx.x * 128;

    int aRow = t >> 1;           // 0..127
    int aCol = (t & 1) * 4;      // 0 or 4
    int bRow = t >> 5;           // 0..7
    int bCol = (t & 31) * 4;     // 0..124

    bool aok = (bm0 + aRow) < NN;
    const float* Aptr = A + (size_t)(bm0 + aRow) * FIN + aCol;
    const float* Bptr = g_B + bRow * CC + bc0 + bCol;

    float4 ar = make_float4(0.f, 0.f, 0.f, 0.f);
    float4 br;
    if (aok) ar = *(const float4*)Aptr;
    br = *(const float4*)Bptr;
    As[0][aCol + 0][aRow] = ar.x;
    As[0][aCol + 1][aRow] = ar.y;
    As[0][aCol + 2][aRow] = ar.z;
    As[0][aCol + 3][aRow] = ar.w;
    *(float4*)&Bs[0][bRow][bCol] = br;
    __syncthreads();

    float acc[8][8];
#pragma unroll
    for (int i = 0; i < 8; i++)
#pragma unroll
        for (int j = 0; j < 8; j++) acc[i][j] = 0.f;

    float af[8], bf[8];

#pragma unroll 1
    for (int kt = 0; kt < 64; kt++) {
        int cur = kt & 1;
        if (kt < 63) {
            if (aok) ar = *(const float4*)(Aptr + (kt + 1) * 8);
            br = *(const float4*)(Bptr + (size_t)(kt + 1) * 8 * CC);
        }
#pragma unroll
        for (int kk = 0; kk < 8; kk++) {
            *(float4*)&af[0] = *(const float4*)&As[cur][kk][ty * 8];
            *(float4*)&af[4] = *(const float4*)&As[cur][kk][ty * 8 + 4];
            *(float4*)&bf[0] = *(const float4*)&Bs[cur][kk][tx * 8];
            *(float4*)&bf[4] = *(const float4*)&Bs[cur][kk][tx * 8 + 4];
#pragma unroll
            for (int i = 0; i < 8; i++)
#pragma unroll
                for (int j = 0; j < 8; j++) acc[i][j] += af[i] * bf[j];
        }
        if (kt < 63) {
            int nxt = cur ^ 1;
            As[nxt][aCol + 0][aRow] = ar.x;
            As[nxt][aCol + 1][aRow] = ar.y;
            As[nxt][aCol + 2][aRow] = ar.z;
            As[nxt][aCol + 3][aRow] = ar.w;
            *(float4*)&Bs[nxt][bRow][bCol] = br;
            __syncthreads();
        }
    }

#pragma unroll
    for (int i = 0; i < 8; i++) {
        int row = bm0 + ty * 8 + i;
        if (row < NN) {
            float* cp = g_h + (size_t)row * CC + bc0 + tx * 8;
            *(float4*)cp       = make_float4(acc[i][0], acc[i][1], acc[i][2], acc[i][3]);
            *(float4*)(cp + 4) = make_float4(acc[i][4], acc[i][5], acc[i][6], acc[i][7]);
        }
    }
}

// ---------------- s_src / s_dst: [N, H] dots of h rows with a vectors ----------------
__global__ void s_kernel(const float* __restrict__ a_src, const float* __restrict__ a_dst) {
    int idx = blockIdx.x * blockDim.x + threadIdx.x;   // n*8 + hd
    if (idx >= NN * HH) return;
    int n = idx >> 3, hd = idx & 7;
    const float4* hp = (const float4*)(g_h + (size_t)n * CC + hd * FO);
    const float4* as = (const float4*)(a_src + hd * FO);
    const float4* ad = (const float4*)(a_dst + hd * FO);
    float s1 = 0.f, s2 = 0.f;
#pragma unroll
    for (int q = 0; q < 8; q++) {
        float4 hv = hp[q], av = as[q], dv = ad[q];
        s1 += hv.x * av.x + hv.y * av.y + hv.z * av.z + hv.w * av.w;
        s2 += hv.x * dv.x + hv.y * dv.y + hv.z * dv.z + hv.w * dv.w;
    }
    g_ssrc[idx] = s1;
    g_sdst[idx] = s2;
}

// ---------------- CSR build ----------------
__global__ void hist_kernel(const int* __restrict__ ei) {
    int e = blockIdx.x * blockDim.x + threadIdx.x;
    if (e < EE) atomicAdd(&g_cnt[ei[EE + e]], 1);
}

__global__ void scan_kernel() {
    // one block, 1024 threads; strips of 40
    __shared__ int sums[1024];
    int t = threadIdx.x;
    int s0 = t * 40;
    int local = 0;
    for (int j = 0; j < 40; j++) {
        int i = s0 + j;
        if (i < NN) local += g_cnt[i];
    }
    sums[t] = local;
    __syncthreads();
    for (int d = 1; d < 1024; d <<= 1) {
        int x = (t >= d) ? sums[t - d] : 0;
        __syncthreads();
        sums[t] += x;
        __syncthreads();
    }
    int run = sums[t] - local;   // exclusive prefix of this strip
    for (int j = 0; j < 40; j++) {
        int i = s0 + j;
        if (i < NN) {
            run += g_cnt[i];
            g_off[i + 1] = run;
        }
    }
    if (t == 0) g_off[0] = 0;
}

__global__ void scatter_kernel(const int* __restrict__ ei) {
    int e = blockIdx.x * blockDim.x + threadIdx.x;
    if (e < EE) {
        int d   = ei[EE + e];
        int pos = g_off[d] + atomicAdd(&g_ctr[d], 1);
        g_csrc[pos] = ei[e];
    }
}

// ---------------- per-dst softmax + aggregation (no atomics) ----------------
#define CH 128
__global__ __launch_bounds__(256) void aggregate_kernel(const float* __restrict__ bias,
                                                        float* __restrict__ out) {
    __shared__ int   sh_src[CH];
    __shared__ float sh_exp[CH * HH];
    __shared__ float sh_sd[HH];

    int dst = blockIdx.x;
    int t   = threadIdx.x;       // 256: t = head*32 + f
    int hd  = t >> 5;

    int beg = g_off[dst];
    int deg = g_off[dst + 1] - beg;

    if (t < HH) sh_sd[t] = g_sdst[dst * HH + t];
    __syncthreads();

    float denom = 0.f, inv = 0.f, acc = 0.f;

#pragma unroll 1
    for (int pass = 0; pass < 2; pass++) {
#pragma unroll 1
        for (int c0 = 0; c0 < deg; c0 += CH) {
            int cl = min(CH, deg - c0);
            if (t < cl) {
                int s = g_csrc[beg + c0 + t];
                sh_src[t] = s;
                float4 v0 = *(const float4*)&g_ssrc[s * HH];
                float4 v1 = *(const float4*)&g_ssrc[s * HH + 4];
                float es[8] = {v0.x, v0.y, v0.z, v0.w, v1.x, v1.y, v1.z, v1.w};
#pragma unroll
                for (int h = 0; h < HH; h++) {
                    float e = es[h] + sh_sd[h];
                    e = (e >= 0.f) ? e : NEG_SLOPE * e;
                    sh_exp[t * HH + h] = __expf(e);
                }
            }
            __syncthreads();
            if (pass == 0) {
                for (int i = 0; i < cl; i++) denom += sh_exp[i * HH + hd];
            } else {
#pragma unroll 4
                for (int i = 0; i < cl; i++) {
                    float alpha = sh_exp[i * HH + hd] * inv;
                    acc += alpha * g_h[(size_t)sh_src[i] * CC + t];
                }
            }
            __syncthreads();
        }
        if (pass == 0) inv = 1.f / (denom + EPS);
    }

    out[(size_t)dst * CC + t] = acc + bias[t];
}

// ---------------- launch ----------------
extern "C" void kernel_launch(void* const* d_in, const int* in_sizes, int n_in,
                              void* d_out, int out_size) {
    const float* x     = (const float*)d_in[0];
    const int*   ei    = (const int*)d_in[1];
    const float* W     = (const float*)d_in[2];
    const float* a_src = (const float*)d_in[3];
    const float* a_dst = (const float*)d_in[4];
    const float* bias  = (const float*)d_in[5];
    float*       out   = (float*)d_out;

    packB_kernel<<<(FIN * CC + 255) / 256, 256>>>(W);
    zero_kernel<<<(NN + 255) / 256, 256>>>();

    dim3 ggrid(CC / 128, (NN + 127) / 128);
    sgemm_kernel<<<ggrid, 256>>>(x);

    s_kernel<<<(NN * HH + 255) / 256, 256>>>(a_src, a_dst);

    hist_kernel<<<(EE + 255) / 256, 256>>>(ei);
    scan_kernel<<<1, 1024>>>();
    scatter_kernel<<<(EE + 255) / 256, 256>>>(ei);

    aggregate_kernel<<<NN, 256>>>(bias, out);
}

// round 2
// speedup vs baseline: 1.8263x; 1.8263x over previous
#include <cuda_runtime.h>
#include <cstdint>

#define NN   40000
#define EE   640000
#define FIN  512
#define HH   8
#define FO   32
#define CC   256          // HH * FO
#define NEG_SLOPE 0.2f
#define EPS  1e-16f

// ---------------- scratch (global device arrays; no allocation) ----------------
__device__ float g_h[NN * CC];        // projected features [N, H*F]
__device__ float g_B[FIN * CC];       // repacked W as [512, 256], tf32-rounded
__device__ float g_ssrc[NN * HH];
__device__ float g_sdst[NN * HH];
__device__ int   g_cnt[NN];
__device__ int   g_ctr[NN];
__device__ int   g_off[NN + 1];
__device__ int   g_csrc[EE];          // src node id per CSR slot (sorted by dst)

__device__ __forceinline__ float to_tf32(float x) {
    float r;
    asm("cvt.rna.tf32.f32 %0, %1;" : "=f"(r) : "f"(x));
    return r;
}

__device__ __forceinline__ void mma_tf32(float* c, const uint32_t* a, const uint32_t* b) {
    asm volatile(
        "mma.sync.aligned.m16n8k8.row.col.f32.tf32.tf32.f32 "
        "{%0,%1,%2,%3}, {%4,%5,%6,%7}, {%8,%9}, {%0,%1,%2,%3};"
        : "+f"(c[0]), "+f"(c[1]), "+f"(c[2]), "+f"(c[3])
        : "r"(a[0]), "r"(a[1]), "r"(a[2]), "r"(a[3]), "r"(b[0]), "r"(b[1]));
}

// ---------------- pack W[H,512,32] -> B[512,256] (tf32-rounded) ----------------
__global__ void packB_kernel(const float* __restrict__ W) {
    int idx = blockIdx.x * blockDim.x + threadIdx.x;
    if (idx < FIN * CC) {
        int d = idx >> 8;          // row (k)
        int c = idx & 255;         // col = head*32 + f
        g_B[idx] = to_tf32(W[(c >> 5) * (FIN * FO) + d * FO + (c & 31)]);
    }
}

__global__ void zero_kernel() {
    int idx = blockIdx.x * blockDim.x + threadIdx.x;
    if (idx < NN) { g_cnt[idx] = 0; g_ctr[idx] = 0; }
}

// ---------------- TF32 tensor-core GEMM: g_h = x(40000x512) * g_B(512x256) ----
// 128x128 tile, BK=16, 256 threads (8 warps), warp tile 64x32 via m16n8k8
__global__ __launch_bounds__(256) void tgemm_kernel(const float* __restrict__ A) {
    __shared__ float As[2][16][132];   // [k][m], padded
    __shared__ float Bs[2][16][132];   // [k][n], padded

    int t    = threadIdx.x;
    int lane = t & 31, warp = t >> 5;
    int gid  = lane >> 2, tid4 = lane & 3;
    int wm   = (warp & 1) * 64;
    int wn   = (warp >> 1) * 32;
    int bm0  = blockIdx.y * 128;
    int bc0  = blockIdx.x * 128;

    // global load mapping
    int aR = t >> 2;                 // 0..63
    int aC = (t & 3) * 4;            // 0,4,8,12
    int bR = t >> 5;                 // 0..7
    int bC = (t & 31) * 4;

    bool ok0 = (bm0 + aR) < NN;
    bool ok1 = (bm0 + aR + 64) < NN;
    const float* Ap0 = A + (size_t)(bm0 + aR) * FIN + aC;
    const float* Ap1 = A + (size_t)(bm0 + aR + 64) * FIN + aC;
    const float* Bp0 = g_B + (size_t)bR * CC + bc0 + bC;
    const float* Bp1 = g_B + (size_t)(bR + 8) * CC + bc0 + bC;

    float4 a0v = ok0 ? *(const float4*)Ap0 : make_float4(0.f, 0.f, 0.f, 0.f);
    float4 a1v = ok1 ? *(const float4*)Ap1 : make_float4(0.f, 0.f, 0.f, 0.f);
    float4 b0v = *(const float4*)Bp0;
    float4 b1v = *(const float4*)Bp1;

    As[0][aC + 0][aR] = to_tf32(a0v.x);
    As[0][aC + 1][aR] = to_tf32(a0v.y);
    As[0][aC + 2][aR] = to_tf32(a0v.z);
    As[0][aC + 3][aR] = to_tf32(a0v.w);
    As[0][aC + 0][aR + 64] = to_tf32(a1v.x);
    As[0][aC + 1][aR + 64] = to_tf32(a1v.y);
    As[0][aC + 2][aR + 64] = to_tf32(a1v.z);
    As[0][aC + 3][aR + 64] = to_tf32(a1v.w);
    *(float4*)&Bs[0][bR][bC]     = b0v;   // already tf32-rounded in packB
    *(float4*)&Bs[0][bR + 8][bC] = b1v;
    __syncthreads();

    float acc[16][4];
#pragma unroll
    for (int i = 0; i < 16; i++)
#pragma unroll
        for (int j = 0; j < 4; j++) acc[i][j] = 0.f;

#pragma unroll 1
    for (int kt = 0; kt < 32; kt++) {
        int cur = kt & 1;
        if (kt < 31) {
            a0v = ok0 ? *(const float4*)(Ap0 + (kt + 1) * 16) : make_float4(0.f, 0.f, 0.f, 0.f);
            a1v = ok1 ? *(const float4*)(Ap1 + (kt + 1) * 16) : make_float4(0.f, 0.f, 0.f, 0.f);
            b0v = *(const float4*)(Bp0 + (size_t)(kt + 1) * 16 * CC);
            b1v = *(const float4*)(Bp1 + (size_t)(kt + 1) * 16 * CC);
        }
#pragma unroll
        for (int ks = 0; ks < 2; ks++) {
            int k0 = ks * 8;
            uint32_t af[4][4], bf[4][2];
#pragma unroll
            for (int mt = 0; mt < 4; mt++) {
                int m = wm + mt * 16 + gid;
                af[mt][0] = __float_as_uint(As[cur][k0 + tid4][m]);
                af[mt][1] = __float_as_uint(As[cur][k0 + tid4][m + 8]);
                af[mt][2] = __float_as_uint(As[cur][k0 + tid4 + 4][m]);
                af[mt][3] = __float_as_uint(As[cur][k0 + tid4 + 4][m + 8]);
            }
#pragma unroll
            for (int nt = 0; nt < 4; nt++) {
                int n = wn + nt * 8 + gid;
                bf[nt][0] = __float_as_uint(Bs[cur][k0 + tid4][n]);
                bf[nt][1] = __float_as_uint(Bs[cur][k0 + tid4 + 4][n]);
            }
#pragma unroll
            for (int mt = 0; mt < 4; mt++)
#pragma unroll
                for (int nt = 0; nt < 4; nt++)
                    mma_tf32(acc[mt * 4 + nt], af[mt], bf[nt]);
        }
        if (kt < 31) {
            int nxt = cur ^ 1;
            As[nxt][aC + 0][aR] = to_tf32(a0v.x);
            As[nxt][aC + 1][aR] = to_tf32(a0v.y);
            As[nxt][aC + 2][aR] = to_tf32(a0v.z);
            As[nxt][aC + 3][aR] = to_tf32(a0v.w);
            As[nxt][aC + 0][aR + 64] = to_tf32(a1v.x);
            As[nxt][aC + 1][aR + 64] = to_tf32(a1v.y);
            As[nxt][aC + 2][aR + 64] = to_tf32(a1v.z);
            As[nxt][aC + 3][aR + 64] = to_tf32(a1v.w);
            *(float4*)&Bs[nxt][bR][bC]     = b0v;
            *(float4*)&Bs[nxt][bR + 8][bC] = b1v;
            __syncthreads();
        }
    }

#pragma unroll
    for (int mt = 0; mt < 4; mt++) {
#pragma unroll
        for (int nt = 0; nt < 4; nt++) {
            int row0 = bm0 + wm + mt * 16 + gid;
            int col  = bc0 + wn + nt * 8 + tid4 * 2;
            float* c = acc[mt * 4 + nt];
            if (row0 < NN)
                *(float2*)&g_h[(size_t)row0 * CC + col] = make_float2(c[0], c[1]);
            if (row0 + 8 < NN)
                *(float2*)&g_h[(size_t)(row0 + 8) * CC + col] = make_float2(c[2], c[3]);
        }
    }
}

// ---------------- s_src/s_dst: warp per node, fully coalesced 1KB row read ----
__global__ __launch_bounds__(256) void s_kernel(const float* __restrict__ a_src,
                                                const float* __restrict__ a_dst) {
    __shared__ float s_as[CC], s_ad[CC];
    int t = threadIdx.x;
    s_as[t] = a_src[t];
    s_ad[t] = a_dst[t];
    __syncthreads();

    int node = (blockIdx.x * blockDim.x + t) >> 5;
    if (node >= NN) return;
    int lane = t & 31;
    int hd = lane >> 2, sub = lane & 3;

    const float* hrow = g_h + (size_t)node * CC + lane * 8;
    float4 v0 = *(const float4*)hrow;
    float4 v1 = *(const float4*)(hrow + 4);
    const float* as = s_as + lane * 8;
    const float* ad = s_ad + lane * 8;

    float s1 = v0.x * as[0] + v0.y * as[1] + v0.z * as[2] + v0.w * as[3]
             + v1.x * as[4] + v1.y * as[5] + v1.z * as[6] + v1.w * as[7];
    float s2 = v0.x * ad[0] + v0.y * ad[1] + v0.z * ad[2] + v0.w * ad[3]
             + v1.x * ad[4] + v1.y * ad[5] + v1.z * ad[6] + v1.w * ad[7];

    s1 += __shfl_xor_sync(0xFFFFFFFF, s1, 1);
    s1 += __shfl_xor_sync(0xFFFFFFFF, s1, 2);
    s2 += __shfl_xor_sync(0xFFFFFFFF, s2, 1);
    s2 += __shfl_xor_sync(0xFFFFFFFF, s2, 2);

    if (sub == 0) {
        g_ssrc[node * HH + hd] = s1;
        g_sdst[node * HH + hd] = s2;
    }
}

// ---------------- CSR build ----------------
__global__ void hist_kernel(const int* __restrict__ ei) {
    int e = blockIdx.x * blockDim.x + threadIdx.x;
    if (e < EE) atomicAdd(&g_cnt[ei[EE + e]], 1);
}

__global__ void scan_kernel() {
    __shared__ int sums[1024];
    int t = threadIdx.x;
    int s0 = t * 40;
    int local = 0;
    for (int j = 0; j < 40; j++) {
        int i = s0 + j;
        if (i < NN) local += g_cnt[i];
    }
    sums[t] = local;
    __syncthreads();
    for (int d = 1; d < 1024; d <<= 1) {
        int x = (t >= d) ? sums[t - d] : 0;
        __syncthreads();
        sums[t] += x;
        __syncthreads();
    }
    int run = sums[t] - local;
    for (int j = 0; j < 40; j++) {
        int i = s0 + j;
        if (i < NN) {
            run += g_cnt[i];
            g_off[i + 1] = run;
        }
    }
    if (t == 0) g_off[0] = 0;
}

__global__ void scatter_kernel(const int* __restrict__ ei) {
    int e = blockIdx.x * blockDim.x + threadIdx.x;
    if (e < EE) {
        int d   = ei[EE + e];
        int pos = g_off[d] + atomicAdd(&g_ctr[d], 1);
        g_csrc[pos] = ei[e];
    }
}

// ---------------- per-dst softmax + aggregation, single fused pass ----------------
// out = (sum_i exp_i * h[src_i]) / (sum_i exp_i + EPS) + bias
#define CH 128
__global__ __launch_bounds__(256) void aggregate_kernel(const float* __restrict__ bias,
                                                        float* __restrict__ out) {
    __shared__ int   sh_src[CH];
    __shared__ float sh_exp[CH * HH];
    __shared__ float sh_sd[HH];

    int dst = blockIdx.x;
    int t   = threadIdx.x;       // 256: t = head*32 + f
    int hd  = t >> 5;

    int beg = g_off[dst];
    int deg = g_off[dst + 1] - beg;

    if (t < HH) sh_sd[t] = g_sdst[dst * HH + t];
    __syncthreads();

    float denom = 0.f, acc = 0.f;

#pragma unroll 1
    for (int c0 = 0; c0 < deg; c0 += CH) {
        int cl = min(CH, deg - c0);
        if (t < cl) {
            int s = g_csrc[beg + c0 + t];
            sh_src[t] = s;
            float4 v0 = *(const float4*)&g_ssrc[s * HH];
            float4 v1 = *(const float4*)&g_ssrc[s * HH + 4];
            float es[8] = {v0.x, v0.y, v0.z, v0.w, v1.x, v1.y, v1.z, v1.w};
#pragma unroll
            for (int h = 0; h < HH; h++) {
                float e = es[h] + sh_sd[h];
                e = (e >= 0.f) ? e : NEG_SLOPE * e;
                sh_exp[t * HH + h] = __expf(e);
            }
        }
        __syncthreads();
#pragma unroll 4
        for (int i = 0; i < cl; i++) {
            float w = sh_exp[i * HH + hd];
            denom += w;
            acc   += w * g_h[(size_t)sh_src[i] * CC + t];
        }
        __syncthreads();
    }

    out[(size_t)dst * CC + t] = acc / (denom + EPS) + bias[t];
}

// ---------------- launch ----------------
extern "C" void kernel_launch(void* const* d_in, const int* in_sizes, int n_in,
                              void* d_out, int out_size) {
    const float* x     = (const float*)d_in[0];
    const int*   ei    = (const int*)d_in[1];
    const float* W     = (const float*)d_in[2];
    const float* a_src = (const float*)d_in[3];
    const float* a_dst = (const float*)d_in[4];
    const float* bias  = (const float*)d_in[5];
    float*       out   = (float*)d_out;

    packB_kernel<<<(FIN * CC + 255) / 256, 256>>>(W);
    zero_kernel<<<(NN + 255) / 256, 256>>>();

    dim3 ggrid(CC / 128, (NN + 127) / 128);
    tgemm_kernel<<<ggrid, 256>>>(x);

    s_kernel<<<(NN * 32 + 255) / 256, 256>>>(a_src, a_dst);

    hist_kernel<<<(EE + 255) / 256, 256>>>(ei);
    scan_kernel<<<1, 1024>>>();
    scatter_kernel<<<(EE + 255) / 256, 256>>>(ei);

    aggregate_kernel<<<NN, 256>>>(bias, out);
}

// round 4
// speedup vs baseline: 2.4452x; 1.3389x over previous
#include <cuda_runtime.h>
#include <cuda_fp16.h>
#include <cstdint>

#define NN   40000
#define EE   640000
#define FIN  512
#define HH   8
#define FO   32
#define CC   256          // HH * FO
#define NEG_SLOPE 0.2f
#define EPS  1e-16f

// ---------------- scratch (global device arrays; no allocation) ----------------
__device__ float  g_h[(size_t)NN * CC];   // projected features [N, H*F]
__device__ __half g_Bh[CC * FIN];         // W repacked as [256 n][512 k], fp16
__device__ float  g_ssrc[NN * HH];
__device__ float  g_sdst[NN * HH];
__device__ int    g_cnt[NN];
__device__ int    g_ctr[NN];
__device__ int    g_off[NN + 1];
__device__ int    g_csrc[EE];

__device__ __forceinline__ void mma_f16(float* c, const uint32_t* a, const uint32_t* b) {
    asm volatile(
        "mma.sync.aligned.m16n8k16.row.col.f32.f16.f16.f32 "
        "{%0,%1,%2,%3}, {%4,%5,%6,%7}, {%8,%9}, {%0,%1,%2,%3};"
        : "+f"(c[0]), "+f"(c[1]), "+f"(c[2]), "+f"(c[3])
        : "r"(a[0]), "r"(a[1]), "r"(a[2]), "r"(a[3]), "r"(b[0]), "r"(b[1]));
}

__device__ __forceinline__ uint2 f4_to_h8(float4 v) {
    __half2 h0 = __floats2half2_rn(v.x, v.y);
    __half2 h1 = __floats2half2_rn(v.z, v.w);
    uint2 u;
    u.x = *(uint32_t*)&h0;
    u.y = *(uint32_t*)&h1;
    return u;
}

// ---------------- pack W[H,512,32] -> Bh[256 n][512 k] fp16 ----------------
__global__ void packBh_kernel(const float* __restrict__ W) {
    int idx = blockIdx.x * blockDim.x + threadIdx.x;   // idx = n*512 + d
    if (idx < CC * FIN) {
        int n = idx >> 9;          // 0..255 = head*32 + f
        int d = idx & 511;
        g_Bh[idx] = __float2half(W[(n >> 5) * (FIN * FO) + d * FO + (n & 31)]);
    }
}

__global__ void zero_kernel() {
    int idx = blockIdx.x * blockDim.x + threadIdx.x;
    if (idx < NN) { g_cnt[idx] = 0; g_ctr[idx] = 0; }
}

// ---------------- fp16 tensor GEMM + fused s epilogue ----------------
// 128x128 tile, BK=32, 256 threads (8 warps), warp tile 64x32 via m16n8k16
// Each warp's 32 cols = exactly one head -> s dots fused in epilogue.
__global__ __launch_bounds__(256) void hgemm_kernel(const float* __restrict__ A,
                                                    const float* __restrict__ a_src,
                                                    const float* __restrict__ a_dst) {
    __shared__ __half As[2][128][40];   // [m][k], padded rows (80B) -> conflict-free
    __shared__ __half Bs[2][128][40];   // [n][k]
    __shared__ float  sh_as[CC], sh_ad[CC];

    int t    = threadIdx.x;
    int lane = t & 31, warp = t >> 5;
    int gid  = lane >> 2, tid4 = lane & 3;
    int wm   = (warp & 1) * 64;
    int wn   = (warp >> 1) * 32;
    int bm0  = blockIdx.y * 128;
    int bc0  = blockIdx.x * 128;

    sh_as[t] = a_src[t];
    sh_ad[t] = a_dst[t];

    // ---- global load mapping ----
    // A: it 0..3, i = t + it*256: r = i>>3 (0..127), c4 = i&7 (float4 within 32 k)
    // B: it 0..1, i = t + it*256: n = i>>2 (0..127), seg = i&3 (8 halves within 32 k)
    float4 av[4];
    uint4  bv[2];

#pragma unroll
    for (int it = 0; it < 4; it++) {
        int i = t + it * 256, r = i >> 3, c4 = i & 7;
        int row = bm0 + r;
        av[it] = (row < NN) ? *(const float4*)(A + (size_t)row * FIN + c4 * 4)
                            : make_float4(0.f, 0.f, 0.f, 0.f);
    }
#pragma unroll
    for (int it = 0; it < 2; it++) {
        int i = t + it * 256, n = i >> 2, seg = i & 3;
        bv[it] = *(const uint4*)(g_Bh + (size_t)(bc0 + n) * FIN + seg * 8);
    }
#pragma unroll
    for (int it = 0; it < 4; it++) {
        int i = t + it * 256, r = i >> 3, c4 = i & 7;
        *(uint2*)&As[0][r][c4 * 4] = f4_to_h8(av[it]);
    }
#pragma unroll
    for (int it = 0; it < 2; it++) {
        int i = t + it * 256, n = i >> 2, seg = i & 3;
        *(uint4*)&Bs[0][n][seg * 8] = bv[it];
    }
    __syncthreads();

    float acc[16][4];
#pragma unroll
    for (int i = 0; i < 16; i++)
#pragma unroll
        for (int j = 0; j < 4; j++) acc[i][j] = 0.f;

#pragma unroll 1
    for (int c = 0; c < 16; c++) {
        int cur = c & 1;
        if (c < 15) {
            int k0 = (c + 1) * 32;
#pragma unroll
            for (int it = 0; it < 4; it++) {
                int i = t + it * 256, r = i >> 3, c4 = i & 7;
                int row = bm0 + r;
                av[it] = (row < NN) ? *(const float4*)(A + (size_t)row * FIN + k0 + c4 * 4)
                                    : make_float4(0.f, 0.f, 0.f, 0.f);
            }
#pragma unroll
            for (int it = 0; it < 2; it++) {
                int i = t + it * 256, n = i >> 2, seg = i & 3;
                bv[it] = *(const uint4*)(g_Bh + (size_t)(bc0 + n) * FIN + k0 + seg * 8);
            }
        }
#pragma unroll
        for (int ks = 0; ks < 2; ks++) {
            int kb = ks * 16;
            uint32_t af[4][4], bf[4][2];
#pragma unroll
            for (int mt = 0; mt < 4; mt++) {
                int row = wm + mt * 16 + gid;
                af[mt][0] = *(const uint32_t*)&As[cur][row][kb + 2 * tid4];
                af[mt][1] = *(const uint32_t*)&As[cur][row + 8][kb + 2 * tid4];
                af[mt][2] = *(const uint32_t*)&As[cur][row][kb + 8 + 2 * tid4];
                af[mt][3] = *(const uint32_t*)&As[cur][row + 8][kb + 8 + 2 * tid4];
            }
#pragma unroll
            for (int nt = 0; nt < 4; nt++) {
                int n = wn + nt * 8 + gid;
                bf[nt][0] = *(const uint32_t*)&Bs[cur][n][kb + 2 * tid4];
                bf[nt][1] = *(const uint32_t*)&Bs[cur][n][kb + 8 + 2 * tid4];
            }
#pragma unroll
            for (int mt = 0; mt < 4; mt++)
#pragma unroll
                for (int nt = 0; nt < 4; nt++)
                    mma_f16(acc[mt * 4 + nt], af[mt], bf[nt]);
        }
        if (c < 15) {
            int nxt = cur ^ 1;
#pragma unroll
            for (int it = 0; it < 4; it++) {
                int i = t + it * 256, r = i >> 3, c4 = i & 7;
                *(uint2*)&As[nxt][r][c4 * 4] = f4_to_h8(av[it]);
            }
#pragma unroll
            for (int it = 0; it < 2; it++) {
                int i = t + it * 256, n = i >> 2, seg = i & 3;
                *(uint4*)&Bs[nxt][n][seg * 8] = bv[it];
            }
            __syncthreads();
        }
    }

    // ---- epilogue: store g_h + fused per-head s_src/s_dst dots ----
    int head = (bc0 + wn) >> 5;
#pragma unroll
    for (int mt = 0; mt < 4; mt++) {
        int row0 = bm0 + wm + mt * 16 + gid;
        float ps0 = 0.f, pd0 = 0.f, ps1 = 0.f, pd1 = 0.f;
#pragma unroll
        for (int nt = 0; nt < 4; nt++) {
            int col = bc0 + wn + nt * 8 + tid4 * 2;
            float* cc = acc[mt * 4 + nt];
            ps0 += cc[0] * sh_as[col] + cc[1] * sh_as[col + 1];
            pd0 += cc[0] * sh_ad[col] + cc[1] * sh_ad[col + 1];
            ps1 += cc[2] * sh_as[col] + cc[3] * sh_as[col + 1];
            pd1 += cc[2] * sh_ad[col] + cc[3] * sh_ad[col + 1];
            if (row0 < NN)
                *(float2*)&g_h[(size_t)row0 * CC + col] = make_float2(cc[0], cc[1]);
            if (row0 + 8 < NN)
                *(float2*)&g_h[(size_t)(row0 + 8) * CC + col] = make_float2(cc[2], cc[3]);
        }
        ps0 += __shfl_xor_sync(0xFFFFFFFF, ps0, 1);
        ps0 += __shfl_xor_sync(0xFFFFFFFF, ps0, 2);
        pd0 += __shfl_xor_sync(0xFFFFFFFF, pd0, 1);
        pd0 += __shfl_xor_sync(0xFFFFFFFF, pd0, 2);
        ps1 += __shfl_xor_sync(0xFFFFFFFF, ps1, 1);
        ps1 += __shfl_xor_sync(0xFFFFFFFF, ps1, 2);
        pd1 += __shfl_xor_sync(0xFFFFFFFF, pd1, 1);
        pd1 += __shfl_xor_sync(0xFFFFFFFF, pd1, 2);
        if (tid4 == 0) {
            if (row0 < NN) {
                g_ssrc[row0 * HH + head] = ps0;
                g_sdst[row0 * HH + head] = pd0;
            }
            if (row0 + 8 < NN) {
                g_ssrc[(row0 + 8) * HH + head] = ps1;
                g_sdst[(row0 + 8) * HH + head] = pd1;
            }
        }
    }
}

// ---------------- CSR build ----------------
__global__ void hist_kernel(const int* __restrict__ ei) {
    int e = blockIdx.x * blockDim.x + threadIdx.x;
    if (e < EE) atomicAdd(&g_cnt[ei[EE + e]], 1);
}

__global__ void scan_kernel() {
    __shared__ int sums[1024];
    int t = threadIdx.x;
    int s0 = t * 40;
    int local = 0;
    for (int j = 0; j < 40; j++) {
        int i = s0 + j;
        if (i < NN) local += g_cnt[i];
    }
    sums[t] = local;
    __syncthreads();
    for (int d = 1; d < 1024; d <<= 1) {
        int v = (t >= d) ? sums[t - d] : 0;
        __syncthreads();
        sums[t] += v;
        __syncthreads();
    }
    int run = sums[t] - local;
    for (int j = 0; j < 40; j++) {
        int i = s0 + j;
        if (i < NN) {
            run += g_cnt[i];
            g_off[i + 1] = run;
        }
    }
    if (t == 0) g_off[0] = 0;
}

__global__ void scatter_kernel(const int* __restrict__ ei) {
    int e = blockIdx.x * blockDim.x + threadIdx.x;
    if (e < EE) {
        int d   = ei[EE + e];
        int pos = g_off[d] + atomicAdd(&g_ctr[d], 1);
        g_csrc[pos] = ei[e];
    }
}

// ---------------- per-dst softmax + aggregation: float4, 4 edges in flight ------
// 4 groups of 64 threads; group g handles edges i = g, g+4, ... ; thread owns 4 cols
#define ACH 64
__global__ __launch_bounds__(256) void aggregate_kernel(const float* __restrict__ bias,
                                                        float* __restrict__ out) {
    __shared__ int   sh_src[ACH];
    __shared__ float sh_exp[ACH][HH];
    __shared__ float sh_sd[HH];
    __shared__ float sh_acc[4][CC];
    __shared__ float sh_den[4][HH];

    int dst = blockIdx.x, t = threadIdx.x;
    int g = t >> 6, q = t & 63;
    int hq = q >> 3;                 // head owning cols q*4..q*4+3

    int beg = g_off[dst];
    int deg = g_off[dst + 1] - beg;

    if (t < HH) sh_sd[t] = g_sdst[dst * HH + t];
    __syncthreads();

    float4 acc = make_float4(0.f, 0.f, 0.f, 0.f);
    float  den = 0.f;

#pragma unroll 1
    for (int c0 = 0; c0 < deg; c0 += ACH) {
        int cl = min(ACH, deg - c0);
        if (t < cl) {
            int s = g_csrc[beg + c0 + t];
            sh_src[t] = s;
            float4 v0 = *(const float4*)&g_ssrc[s * HH];
            float4 v1 = *(const float4*)&g_ssrc[s * HH + 4];
            float es[8] = {v0.x, v0.y, v0.z, v0.w, v1.x, v1.y, v1.z, v1.w};
#pragma unroll
            for (int h = 0; h < HH; h++) {
                float e = es[h] + sh_sd[h];
                e = (e >= 0.f) ? e : NEG_SLOPE * e;
                sh_exp[t][h] = __expf(e);
            }
        }
        __syncthreads();
#pragma unroll 2
        for (int i = g; i < cl; i += 4) {
            float wgt = sh_exp[i][hq];
            float4 hv = *(const float4*)(g_h + (size_t)sh_src[i] * CC + q * 4);
            acc.x += wgt * hv.x;
            acc.y += wgt * hv.y;
            acc.z += wgt * hv.z;
            acc.w += wgt * hv.w;
            den   += wgt;
        }
        __syncthreads();
    }

    *(float4*)&sh_acc[g][q * 4] = acc;
    if ((q & 7) == 0) sh_den[g][hq] = den;
    __syncthreads();

    float a  = sh_acc[0][t] + sh_acc[1][t] + sh_acc[2][t] + sh_acc[3][t];
    int   hd = t >> 5;
    float d  = sh_den[0][hd] + sh_den[1][hd] + sh_den[2][hd] + sh_den[3][hd];
    out[(size_t)dst * CC + t] = a / (d + EPS) + bias[t];
}

// ---------------- launch ----------------
extern "C" void kernel_launch(void* const* d_in, const int* in_sizes, int n_in,
                              void* d_out, int out_size) {
    const float* x     = (const float*)d_in[0];
    const int*   ei    = (const int*)d_in[1];
    const float* W     = (const float*)d_in[2];
    const float* a_src = (const float*)d_in[3];
    const float* a_dst = (const float*)d_in[4];
    const float* bias  = (const float*)d_in[5];
    float*       out   = (float*)d_out;

    packBh_kernel<<<(CC * FIN + 255) / 256, 256>>>(W);
    zero_kernel<<<(NN + 255) / 256, 256>>>();

    dim3 ggrid(CC / 128, (NN + 127) / 128);
    hgemm_kernel<<<ggrid, 256>>>(x, a_src, a_dst);

    hist_kernel<<<(EE + 255) / 256, 256>>>(ei);
    scan_kernel<<<1, 1024>>>();
    scatter_kernel<<<(EE + 255) / 256, 256>>>(ei);

    aggregate_kernel<<<NN, 256>>>(bias, out);
}

// round 5
// speedup vs baseline: 3.2652x; 1.3353x over previous
#include <cuda_runtime.h>
#include <cuda_fp16.h>
#include <cstdint>

#define NN   40000
#define EE   640000
#define FIN  512
#define HH   8
#define FO   32
#define CC   256          // HH * FO
#define NEG_SLOPE 0.2f
#define EPS  1e-16f

// ---------------- scratch (global device arrays; no allocation) ----------------
__device__ __half g_hh[(size_t)NN * CC]; // projected features [N, H*F], fp16
__device__ __half g_Bh[CC * FIN];        // W repacked as [256 n][512 k], fp16
__device__ float  g_ssrc[NN * HH];
__device__ float  g_sdst[NN * HH];
__device__ int    g_cnt[NN];
__device__ int    g_ctr[NN];
__device__ int    g_off[NN + 1];
__device__ int    g_csrc[EE];

__device__ __forceinline__ void mma_f16(float* c, const uint32_t* a, const uint32_t* b) {
    asm volatile(
        "mma.sync.aligned.m16n8k16.row.col.f32.f16.f16.f32 "
        "{%0,%1,%2,%3}, {%4,%5,%6,%7}, {%8,%9}, {%0,%1,%2,%3};"
        : "+f"(c[0]), "+f"(c[1]), "+f"(c[2]), "+f"(c[3])
        : "r"(a[0]), "r"(a[1]), "r"(a[2]), "r"(a[3]), "r"(b[0]), "r"(b[1]));
}

__device__ __forceinline__ uint2 f4_to_h8(float4 v) {
    __half2 h0 = __floats2half2_rn(v.x, v.y);
    __half2 h1 = __floats2half2_rn(v.z, v.w);
    uint2 u;
    u.x = *(uint32_t*)&h0;
    u.y = *(uint32_t*)&h1;
    return u;
}

// ---------------- pack W[H,512,32] -> Bh[256 n][512 k] fp16 ----------------
__global__ void packBh_kernel(const float* __restrict__ W) {
    int idx = blockIdx.x * blockDim.x + threadIdx.x;   // idx = n*512 + d
    if (idx < CC * FIN) {
        int n = idx >> 9;          // 0..255 = head*32 + f
        int d = idx & 511;
        g_Bh[idx] = __float2half(W[(n >> 5) * (FIN * FO) + d * FO + (n & 31)]);
    }
}

__global__ void zero_kernel() {
    int idx = blockIdx.x * blockDim.x + threadIdx.x;
    if (idx < NN) { g_cnt[idx] = 0; g_ctr[idx] = 0; }
}

// ---------------- fp16 tensor GEMM + fused s epilogue ----------------
// 128x128 tile, BK=32, 256 threads (8 warps), warp tile 64x32 via m16n8k16
__global__ __launch_bounds__(256) void hgemm_kernel(const float* __restrict__ A,
                                                    const float* __restrict__ a_src,
                                                    const float* __restrict__ a_dst) {
    __shared__ __half As[2][128][40];   // [m][k], padded rows -> conflict-free
    __shared__ __half Bs[2][128][40];   // [n][k]
    __shared__ float  sh_as[CC], sh_ad[CC];

    int t    = threadIdx.x;
    int lane = t & 31, warp = t >> 5;
    int gid  = lane >> 2, tid4 = lane & 3;
    int wm   = (warp & 1) * 64;
    int wn   = (warp >> 1) * 32;
    int bm0  = blockIdx.y * 128;
    int bc0  = blockIdx.x * 128;

    sh_as[t] = a_src[t];
    sh_ad[t] = a_dst[t];

    float4 av[4];
    uint4  bv[2];

#pragma unroll
    for (int it = 0; it < 4; it++) {
        int i = t + it * 256, r = i >> 3, c4 = i & 7;
        int row = bm0 + r;
        av[it] = (row < NN) ? *(const float4*)(A + (size_t)row * FIN + c4 * 4)
                            : make_float4(0.f, 0.f, 0.f, 0.f);
    }
#pragma unroll
    for (int it = 0; it < 2; it++) {
        int i = t + it * 256, n = i >> 2, seg = i & 3;
        bv[it] = *(const uint4*)(g_Bh + (size_t)(bc0 + n) * FIN + seg * 8);
    }
#pragma unroll
    for (int it = 0; it < 4; it++) {
        int i = t + it * 256, r = i >> 3, c4 = i & 7;
        *(uint2*)&As[0][r][c4 * 4] = f4_to_h8(av[it]);
    }
#pragma unroll
    for (int it = 0; it < 2; it++) {
        int i = t + it * 256, n = i >> 2, seg = i & 3;
        *(uint4*)&Bs[0][n][seg * 8] = bv[it];
    }
    __syncthreads();

    float acc[16][4];
#pragma unroll
    for (int i = 0; i < 16; i++)
#pragma unroll
        for (int j = 0; j < 4; j++) acc[i][j] = 0.f;

#pragma unroll 1
    for (int c = 0; c < 16; c++) {
        int cur = c & 1;
        if (c < 15) {
            int k0 = (c + 1) * 32;
#pragma unroll
            for (int it = 0; it < 4; it++) {
                int i = t + it * 256, r = i >> 3, c4 = i & 7;
                int row = bm0 + r;
                av[it] = (row < NN) ? *(const float4*)(A + (size_t)row * FIN + k0 + c4 * 4)
                                    : make_float4(0.f, 0.f, 0.f, 0.f);
            }
#pragma unroll
            for (int it = 0; it < 2; it++) {
                int i = t + it * 256, n = i >> 2, seg = i & 3;
                bv[it] = *(const uint4*)(g_Bh + (size_t)(bc0 + n) * FIN + k0 + seg * 8);
            }
        }
#pragma unroll
        for (int ks = 0; ks < 2; ks++) {
            int kb = ks * 16;
            uint32_t af[4][4], bf[4][2];
#pragma unroll
            for (int mt = 0; mt < 4; mt++) {
                int row = wm + mt * 16 + gid;
                af[mt][0] = *(const uint32_t*)&As[cur][row][kb + 2 * tid4];
                af[mt][1] = *(const uint32_t*)&As[cur][row + 8][kb + 2 * tid4];
                af[mt][2] = *(const uint32_t*)&As[cur][row][kb + 8 + 2 * tid4];
                af[mt][3] = *(const uint32_t*)&As[cur][row + 8][kb + 8 + 2 * tid4];
            }
#pragma unroll
            for (int nt = 0; nt < 4; nt++) {
                int n = wn + nt * 8 + gid;
                bf[nt][0] = *(const uint32_t*)&Bs[cur][n][kb + 2 * tid4];
                bf[nt][1] = *(const uint32_t*)&Bs[cur][n][kb + 8 + 2 * tid4];
            }
#pragma unroll
            for (int mt = 0; mt < 4; mt++)
#pragma unroll
                for (int nt = 0; nt < 4; nt++)
                    mma_f16(acc[mt * 4 + nt], af[mt], bf[nt]);
        }
        if (c < 15) {
            int nxt = cur ^ 1;
#pragma unroll
            for (int it = 0; it < 4; it++) {
                int i = t + it * 256, r = i >> 3, c4 = i & 7;
                *(uint2*)&As[nxt][r][c4 * 4] = f4_to_h8(av[it]);
            }
#pragma unroll
            for (int it = 0; it < 2; it++) {
                int i = t + it * 256, n = i >> 2, seg = i & 3;
                *(uint4*)&Bs[nxt][n][seg * 8] = bv[it];
            }
            __syncthreads();
        }
    }

    // ---- epilogue: store g_hh (fp16) + fused per-head s_src/s_dst dots ----
    int head = (bc0 + wn) >> 5;
#pragma unroll
    for (int mt = 0; mt < 4; mt++) {
        int row0 = bm0 + wm + mt * 16 + gid;
        float ps0 = 0.f, pd0 = 0.f, ps1 = 0.f, pd1 = 0.f;
#pragma unroll
        for (int nt = 0; nt < 4; nt++) {
            int col = bc0 + wn + nt * 8 + tid4 * 2;
            float* cc = acc[mt * 4 + nt];
            ps0 += cc[0] * sh_as[col] + cc[1] * sh_as[col + 1];
            pd0 += cc[0] * sh_ad[col] + cc[1] * sh_ad[col + 1];
            ps1 += cc[2] * sh_as[col] + cc[3] * sh_as[col + 1];
            pd1 += cc[2] * sh_ad[col] + cc[3] * sh_ad[col + 1];
            if (row0 < NN)
                *(__half2*)&g_hh[(size_t)row0 * CC + col] = __floats2half2_rn(cc[0], cc[1]);
            if (row0 + 8 < NN)
                *(__half2*)&g_hh[(size_t)(row0 + 8) * CC + col] = __floats2half2_rn(cc[2], cc[3]);
        }
        ps0 += __shfl_xor_sync(0xFFFFFFFF, ps0, 1);
        ps0 += __shfl_xor_sync(0xFFFFFFFF, ps0, 2);
        pd0 += __shfl_xor_sync(0xFFFFFFFF, pd0, 1);
        pd0 += __shfl_xor_sync(0xFFFFFFFF, pd0, 2);
        ps1 += __shfl_xor_sync(0xFFFFFFFF, ps1, 1);
        ps1 += __shfl_xor_sync(0xFFFFFFFF, ps1, 2);
        pd1 += __shfl_xor_sync(0xFFFFFFFF, pd1, 1);
        pd1 += __shfl_xor_sync(0xFFFFFFFF, pd1, 2);
        if (tid4 == 0) {
            if (row0 < NN) {
                g_ssrc[row0 * HH + head] = ps0;
                g_sdst[row0 * HH + head] = pd0;
            }
            if (row0 + 8 < NN) {
                g_ssrc[(row0 + 8) * HH + head] = ps1;
                g_sdst[(row0 + 8) * HH + head] = pd1;
            }
        }
    }
}

// ---------------- CSR build (int4-vectorized) ----------------
__global__ void hist_kernel(const int* __restrict__ ei) {
    int q = blockIdx.x * blockDim.x + threadIdx.x;
    if (q < EE / 4) {
        int4 d = *(const int4*)(ei + EE + q * 4);
        atomicAdd(&g_cnt[d.x], 1);
        atomicAdd(&g_cnt[d.y], 1);
        atomicAdd(&g_cnt[d.z], 1);
        atomicAdd(&g_cnt[d.w], 1);
    }
}

__global__ void scan_kernel() {
    __shared__ int sums[1024];
    int t = threadIdx.x;
    int s0 = t * 40;
    int local = 0;
    for (int j = 0; j < 40; j++) {
        int i = s0 + j;
        if (i < NN) local += g_cnt[i];
    }
    sums[t] = local;
    __syncthreads();
    for (int d = 1; d < 1024; d <<= 1) {
        int v = (t >= d) ? sums[t - d] : 0;
        __syncthreads();
        sums[t] += v;
        __syncthreads();
    }
    int run = sums[t] - local;
    for (int j = 0; j < 40; j++) {
        int i = s0 + j;
        if (i < NN) {
            run += g_cnt[i];
            g_off[i + 1] = run;
        }
    }
    if (t == 0) g_off[0] = 0;
}

__global__ void scatter_kernel(const int* __restrict__ ei) {
    int q = blockIdx.x * blockDim.x + threadIdx.x;
    if (q < EE / 4) {
        int4 s = *(const int4*)(ei + q * 4);
        int4 d = *(const int4*)(ei + EE + q * 4);
        g_csrc[g_off[d.x] + atomicAdd(&g_ctr[d.x], 1)] = s.x;
        g_csrc[g_off[d.y] + atomicAdd(&g_ctr[d.y], 1)] = s.y;
        g_csrc[g_off[d.z] + atomicAdd(&g_ctr[d.z], 1)] = s.z;
        g_csrc[g_off[d.w] + atomicAdd(&g_ctr[d.w], 1)] = s.w;
    }
}

// ---------------- warp-per-dst softmax + aggregation (fp16 h) ----------------
// lane owns 8 cols (16B uint4 per edge row); den identical in all lanes.
#define AW 8
__global__ __launch_bounds__(256) void aggregate_kernel(const float* __restrict__ bias,
                                                        float* __restrict__ out) {
    __shared__ float sh_exp[AW][32][9];   // padded: stride 9 -> conflict-free writes
    __shared__ int   sh_src[AW][32];

    int t = threadIdx.x, w = t >> 5, lane = t & 31;
    int dst = blockIdx.x * AW + w;
    if (dst >= NN) return;
    int hd = lane >> 2;

    int beg = g_off[dst];
    int deg = g_off[dst + 1] - beg;

    float4 sd0 = *(const float4*)&g_sdst[dst * HH];
    float4 sd1 = *(const float4*)&g_sdst[dst * HH + 4];

    float acc[8] = {0.f, 0.f, 0.f, 0.f, 0.f, 0.f, 0.f, 0.f};
    float den = 0.f;

#pragma unroll 1
    for (int c0 = 0; c0 < deg; c0 += 32) {
        int cl = min(32, deg - c0);
        if (lane < cl) {
            int s = g_csrc[beg + c0 + lane];
            sh_src[w][lane] = s;
            float4 v0 = *(const float4*)&g_ssrc[s * HH];
            float4 v1 = *(const float4*)&g_ssrc[s * HH + 4];
            float es[8] = {v0.x + sd0.x, v0.y + sd0.y, v0.z + sd0.z, v0.w + sd0.w,
                           v1.x + sd1.x, v1.y + sd1.y, v1.z + sd1.z, v1.w + sd1.w};
#pragma unroll
            for (int h = 0; h < HH; h++) {
                float e = es[h];
                e = (e >= 0.f) ? e : NEG_SLOPE * e;
                sh_exp[w][lane][h] = __expf(e);
            }
        }
        __syncwarp();
#pragma unroll 4
        for (int i = 0; i < cl; i++) {
            float wgt = sh_exp[w][i][hd];
            uint4 u = *(const uint4*)(g_hh + (size_t)sh_src[w][i] * CC + lane * 8);
            __half2* hp = (__half2*)&u;
            float2 f0 = __half22float2(hp[0]);
            float2 f1 = __half22float2(hp[1]);
            float2 f2 = __half22float2(hp[2]);
            float2 f3 = __half22float2(hp[3]);
            acc[0] += wgt * f0.x; acc[1] += wgt * f0.y;
            acc[2] += wgt * f1.x; acc[3] += wgt * f1.y;
            acc[4] += wgt * f2.x; acc[5] += wgt * f2.y;
            acc[6] += wgt * f3.x; acc[7] += wgt * f3.y;
            den += wgt;
        }
        __syncwarp();
    }

    float inv = 1.f / (den + EPS);
    const float* bp = bias + lane * 8;
    float4 b0 = *(const float4*)bp;
    float4 b1 = *(const float4*)(bp + 4);
    float* op = out + (size_t)dst * CC + lane * 8;
    *(float4*)op = make_float4(acc[0] * inv + b0.x, acc[1] * inv + b0.y,
                               acc[2] * inv + b0.z, acc[3] * inv + b0.w);
    *(float4*)(op + 4) = make_float4(acc[4] * inv + b1.x, acc[5] * inv + b1.y,
                                     acc[6] * inv + b1.z, acc[7] * inv + b1.w);
}

// ---------------- launch ----------------
extern "C" void kernel_launch(void* const* d_in, const int* in_sizes, int n_in,
                              void* d_out, int out_size) {
    const float* x     = (const float*)d_in[0];
    const int*   ei    = (const int*)d_in[1];
    const float* W     = (const float*)d_in[2];
    const float* a_src = (const float*)d_in[3];
    const float* a_dst = (const float*)d_in[4];
    const float* bias  = (const float*)d_in[5];
    float*       out   = (float*)d_out;

    packBh_kernel<<<(CC * FIN + 255) / 256, 256>>>(W);
    zero_kernel<<<(NN + 255) / 256, 256>>>();

    dim3 ggrid(CC / 128, (NN + 127) / 128);
    hgemm_kernel<<<ggrid, 256>>>(x, a_src, a_dst);

    hist_kernel<<<(EE / 4 + 255) / 256, 256>>>(ei);
    scan_kernel<<<1, 1024>>>();
    scatter_kernel<<<(EE / 4 + 255) / 256, 256>>>(ei);

    aggregate_kernel<<<(NN + AW - 1) / AW, 256>>>(bias, out);
}

// round 6
// speedup vs baseline: 3.3156x; 1.0154x over previous
#include <cuda_runtime.h>
#include <cuda_fp16.h>
#include <cstdint>

#define NN   40000
#define EE   640000
#define FIN  512
#define HH   8
#define FO   32
#define CC   256          // HH * FO
#define NEG_SLOPE 0.2f
#define EPS  1e-16f

// ---------------- scratch (global device arrays; no allocation) ----------------
__device__ __half g_hh[(size_t)NN * CC]; // projected features [N, H*F], fp16
__device__ __half g_Bh[CC * FIN];        // W repacked as [256 n][512 k], fp16
__device__ float  g_ssrc[NN * HH];
__device__ float  g_sdst[NN * HH];
__device__ int    g_cnt[NN];
__device__ int    g_ctr[NN];
__device__ int    g_off[NN + 1];
__device__ int    g_csrc[EE];

__device__ __forceinline__ void mma_f16(float* c, const uint32_t* a, const uint32_t* b) {
    asm volatile(
        "mma.sync.aligned.m16n8k16.row.col.f32.f16.f16.f32 "
        "{%0,%1,%2,%3}, {%4,%5,%6,%7}, {%8,%9}, {%0,%1,%2,%3};"
        : "+f"(c[0]), "+f"(c[1]), "+f"(c[2]), "+f"(c[3])
        : "r"(a[0]), "r"(a[1]), "r"(a[2]), "r"(a[3]), "r"(b[0]), "r"(b[1]));
}

__device__ __forceinline__ void ldsm_x4(uint32_t* r, uint32_t addr) {
    asm volatile("ldmatrix.sync.aligned.m8n8.x4.shared.b16 {%0,%1,%2,%3}, [%4];"
        : "=r"(r[0]), "=r"(r[1]), "=r"(r[2]), "=r"(r[3]) : "r"(addr));
}

__device__ __forceinline__ uint2 f4_to_h8(float4 v) {
    __half2 h0 = __floats2half2_rn(v.x, v.y);
    __half2 h1 = __floats2half2_rn(v.z, v.w);
    uint2 u;
    u.x = *(uint32_t*)&h0;
    u.y = *(uint32_t*)&h1;
    return u;
}

// ---------------- setup: pack W -> Bh fp16, zero counters ----------------
__global__ void setup_kernel(const float* __restrict__ W) {
    int idx = blockIdx.x * blockDim.x + threadIdx.x;
    if (idx < CC * FIN) {
        int n = idx >> 9;          // 0..255 = head*32 + f
        int d = idx & 511;
        g_Bh[idx] = __float2half(W[(n >> 5) * (FIN * FO) + d * FO + (n & 31)]);
    }
    if (idx < NN) { g_cnt[idx] = 0; g_ctr[idx] = 0; }
}

// ---------------- fp16 tensor GEMM + fused s epilogue ----------------
// 128x128 tile, BK=32, 256 threads (8 warps), warp tile 64x32 via m16n8k16
__global__ __launch_bounds__(256) void hgemm_kernel(const float* __restrict__ A,
                                                    const float* __restrict__ a_src,
                                                    const float* __restrict__ a_dst) {
    __shared__ __half As[2][128][40];   // [m][k], 80B rows -> ldmatrix conflict-free
    __shared__ __half Bs[2][128][40];   // [n][k]
    __shared__ float  sh_as[CC], sh_ad[CC];

    int t    = threadIdx.x;
    int lane = t & 31, warp = t >> 5;
    int gid  = lane >> 2, tid4 = lane & 3;
    int wm   = (warp & 1) * 64;
    int wn   = (warp >> 1) * 32;
    int bm0  = blockIdx.y * 128;
    int bc0  = blockIdx.x * 128;

    sh_as[t] = a_src[t];
    sh_ad[t] = a_dst[t];

    uint32_t as_u32 = (uint32_t)__cvta_generic_to_shared(&As[0][0][0]);
    uint32_t bs_u32 = (uint32_t)__cvta_generic_to_shared(&Bs[0][0][0]);
    // ldmatrix per-lane row/col mapping (see m16n8k16 fragment spec)
    int ra   = wm + (lane & 15);          // + mt*16
    int kaof = (lane >> 4) << 3;
    int rb   = wn + ((lane >> 4) << 3) + (lane & 7);   // + p*16
    int kbof = ((lane >> 3) & 1) << 3;

    float4 av[4];
    uint4  bv[2];

#pragma unroll
    for (int it = 0; it < 4; it++) {
        int i = t + it * 256, r = i >> 3, c4 = i & 7;
        int row = bm0 + r;
        av[it] = (row < NN) ? *(const float4*)(A + (size_t)row * FIN + c4 * 4)
                            : make_float4(0.f, 0.f, 0.f, 0.f);
    }
#pragma unroll
    for (int it = 0; it < 2; it++) {
        int i = t + it * 256, n = i >> 2, seg = i & 3;
        bv[it] = *(const uint4*)(g_Bh + (size_t)(bc0 + n) * FIN + seg * 8);
    }
#pragma unroll
    for (int it = 0; it < 4; it++) {
        int i = t + it * 256, r = i >> 3, c4 = i & 7;
        *(uint2*)&As[0][r][c4 * 4] = f4_to_h8(av[it]);
    }
#pragma unroll
    for (int it = 0; it < 2; it++) {
        int i = t + it * 256, n = i >> 2, seg = i & 3;
        *(uint4*)&Bs[0][n][seg * 8] = bv[it];
    }
    __syncthreads();

    float acc[16][4];
#pragma unroll
    for (int i = 0; i < 16; i++)
#pragma unroll
        for (int j = 0; j < 4; j++) acc[i][j] = 0.f;

#pragma unroll 1
    for (int c = 0; c < 16; c++) {
        int cur = c & 1;
        if (c < 15) {
            int k0 = (c + 1) * 32;
#pragma unroll
            for (int it = 0; it < 4; it++) {
                int i = t + it * 256, r = i >> 3, c4 = i & 7;
                int row = bm0 + r;
                av[it] = (row < NN) ? *(const float4*)(A + (size_t)row * FIN + k0 + c4 * 4)
                                    : make_float4(0.f, 0.f, 0.f, 0.f);
            }
#pragma unroll
            for (int it = 0; it < 2; it++) {
                int i = t + it * 256, n = i >> 2, seg = i & 3;
                bv[it] = *(const uint4*)(g_Bh + (size_t)(bc0 + n) * FIN + k0 + seg * 8);
            }
        }
        uint32_t abase = as_u32 + (uint32_t)cur * 10240;
        uint32_t bbase = bs_u32 + (uint32_t)cur * 10240;
#pragma unroll
        for (int ks = 0; ks < 2; ks++) {
            int kb = ks * 16;
            uint32_t af[4][4], bf[4][2];
#pragma unroll
            for (int mt = 0; mt < 4; mt++)
                ldsm_x4(af[mt], abase + (uint32_t)(((ra + mt * 16) * 40 + kb + kaof) * 2));
#pragma unroll
            for (int p = 0; p < 2; p++) {
                uint32_t tmp[4];
                ldsm_x4(tmp, bbase + (uint32_t)(((rb + p * 16) * 40 + kb + kbof) * 2));
                bf[2 * p][0]     = tmp[0];
                bf[2 * p][1]     = tmp[1];
                bf[2 * p + 1][0] = tmp[2];
                bf[2 * p + 1][1] = tmp[3];
            }
#pragma unroll
            for (int mt = 0; mt < 4; mt++)
#pragma unroll
                for (int nt = 0; nt < 4; nt++)
                    mma_f16(acc[mt * 4 + nt], af[mt], bf[nt]);
        }
        if (c < 15) {
            int nxt = cur ^ 1;
#pragma unroll
            for (int it = 0; it < 4; it++) {
                int i = t + it * 256, r = i >> 3, c4 = i & 7;
                *(uint2*)&As[nxt][r][c4 * 4] = f4_to_h8(av[it]);
            }
#pragma unroll
            for (int it = 0; it < 2; it++) {
                int i = t + it * 256, n = i >> 2, seg = i & 3;
                *(uint4*)&Bs[nxt][n][seg * 8] = bv[it];
            }
            __syncthreads();
        }
    }

    // ---- epilogue: store g_hh (fp16) + fused per-head s_src/s_dst dots ----
    int head = (bc0 + wn) >> 5;
#pragma unroll
    for (int mt = 0; mt < 4; mt++) {
        int row0 = bm0 + wm + mt * 16 + gid;
        float ps0 = 0.f, pd0 = 0.f, ps1 = 0.f, pd1 = 0.f;
#pragma unroll
        for (int nt = 0; nt < 4; nt++) {
            int col = bc0 + wn + nt * 8 + tid4 * 2;
            float* cc = acc[mt * 4 + nt];
            ps0 += cc[0] * sh_as[col] + cc[1] * sh_as[col + 1];
            pd0 += cc[0] * sh_ad[col] + cc[1] * sh_ad[col + 1];
            ps1 += cc[2] * sh_as[col] + cc[3] * sh_as[col + 1];
            pd1 += cc[2] * sh_ad[col] + cc[3] * sh_ad[col + 1];
            if (row0 < NN)
                *(__half2*)&g_hh[(size_t)row0 * CC + col] = __floats2half2_rn(cc[0], cc[1]);
            if (row0 + 8 < NN)
                *(__half2*)&g_hh[(size_t)(row0 + 8) * CC + col] = __floats2half2_rn(cc[2], cc[3]);
        }
        ps0 += __shfl_xor_sync(0xFFFFFFFF, ps0, 1);
        ps0 += __shfl_xor_sync(0xFFFFFFFF, ps0, 2);
        pd0 += __shfl_xor_sync(0xFFFFFFFF, pd0, 1);
        pd0 += __shfl_xor_sync(0xFFFFFFFF, pd0, 2);
        ps1 += __shfl_xor_sync(0xFFFFFFFF, ps1, 1);
        ps1 += __shfl_xor_sync(0xFFFFFFFF, ps1, 2);
        pd1 += __shfl_xor_sync(0xFFFFFFFF, pd1, 1);
        pd1 += __shfl_xor_sync(0xFFFFFFFF, pd1, 2);
        if (tid4 == 0) {
            if (row0 < NN) {
                g_ssrc[row0 * HH + head] = ps0;
                g_sdst[row0 * HH + head] = pd0;
            }
            if (row0 + 8 < NN) {
                g_ssrc[(row0 + 8) * HH + head] = ps1;
                g_sdst[(row0 + 8) * HH + head] = pd1;
            }
        }
    }
}

// ---------------- CSR build (int4-vectorized) ----------------
__global__ void hist_kernel(const int* __restrict__ ei) {
    int q = blockIdx.x * blockDim.x + threadIdx.x;
    if (q < EE / 4) {
        int4 d = *(const int4*)(ei + EE + q * 4);
        atomicAdd(&g_cnt[d.x], 1);
        atomicAdd(&g_cnt[d.y], 1);
        atomicAdd(&g_cnt[d.z], 1);
        atomicAdd(&g_cnt[d.w], 1);
    }
}

__global__ void scan_kernel() {
    __shared__ int sums[1024];
    int t = threadIdx.x;
    int s0 = t * 40;
    int local = 0;
    for (int j = 0; j < 40; j++) {
        int i = s0 + j;
        if (i < NN) local += g_cnt[i];
    }
    sums[t] = local;
    __syncthreads();
    for (int d = 1; d < 1024; d <<= 1) {
        int v = (t >= d) ? sums[t - d] : 0;
        __syncthreads();
        sums[t] += v;
        __syncthreads();
    }
    int run = sums[t] - local;
    for (int j = 0; j < 40; j++) {
        int i = s0 + j;
        if (i < NN) {
            run += g_cnt[i];
            g_off[i + 1] = run;
        }
    }
    if (t == 0) g_off[0] = 0;
}

__global__ void scatter_kernel(const int* __restrict__ ei) {
    int q = blockIdx.x * blockDim.x + threadIdx.x;
    if (q < EE / 4) {
        int4 s = *(const int4*)(ei + q * 4);
        int4 d = *(const int4*)(ei + EE + q * 4);
        g_csrc[g_off[d.x] + atomicAdd(&g_ctr[d.x], 1)] = s.x;
        g_csrc[g_off[d.y] + atomicAdd(&g_ctr[d.y], 1)] = s.y;
        g_csrc[g_off[d.z] + atomicAdd(&g_ctr[d.z], 1)] = s.z;
        g_csrc[g_off[d.w] + atomicAdd(&g_ctr[d.w], 1)] = s.w;
    }
}

// ---------------- warp-per-dst softmax + aggregation (fp16 h, MLP-8) ----------------
#define AW 8
__global__ __launch_bounds__(256) void aggregate_kernel(const float* __restrict__ bias,
                                                        float* __restrict__ out) {
    __shared__ float sh_exp[AW][32][9];
    __shared__ int   sh_src[AW][32];

    int t = threadIdx.x, w = t >> 5, lane = t & 31;
    int dst = blockIdx.x * AW + w;
    if (dst >= NN) return;
    int hd = lane >> 2;

    int beg = g_off[dst];
    int deg = g_off[dst + 1] - beg;

    float4 sd0 = *(const float4*)&g_sdst[dst * HH];
    float4 sd1 = *(const float4*)&g_sdst[dst * HH + 4];

    float acc[8] = {0.f, 0.f, 0.f, 0.f, 0.f, 0.f, 0.f, 0.f};
    float den = 0.f;

#pragma unroll 1
    for (int c0 = 0; c0 < deg; c0 += 32) {
        int cl = min(32, deg - c0);
        if (lane < cl) {
            int s = g_csrc[beg + c0 + lane];
            sh_src[w][lane] = s;
            float4 v0 = *(const float4*)&g_ssrc[s * HH];
            float4 v1 = *(const float4*)&g_ssrc[s * HH + 4];
            float es[8] = {v0.x + sd0.x, v0.y + sd0.y, v0.z + sd0.z, v0.w + sd0.w,
                           v1.x + sd1.x, v1.y + sd1.y, v1.z + sd1.z, v1.w + sd1.w};
#pragma unroll
            for (int h = 0; h < HH; h++) {
                float e = es[h];
                e = (e >= 0.f) ? e : NEG_SLOPE * e;
                sh_exp[w][lane][h] = __expf(e);
            }
        }
        __syncwarp();
#pragma unroll 1
        for (int i = 0; i < cl; i += 8) {
            int   srcs[8];
            float wg[8];
#pragma unroll
            for (int j = 0; j < 8; j++) {
                int  ij = i + j;
                bool v  = ij < cl;
                int  si = v ? ij : 0;
                srcs[j] = sh_src[w][si];
                wg[j]   = v ? sh_exp[w][si][hd] : 0.f;
            }
            uint4 u[8];
#pragma unroll
            for (int j = 0; j < 8; j++)
                u[j] = *(const uint4*)(g_hh + (size_t)srcs[j] * CC + lane * 8);
#pragma unroll
            for (int j = 0; j < 8; j++) {
                __half2* hp = (__half2*)&u[j];
                float2 f0 = __half22float2(hp[0]);
                float2 f1 = __half22float2(hp[1]);
                float2 f2 = __half22float2(hp[2]);
                float2 f3 = __half22float2(hp[3]);
                float wgt = wg[j];
                acc[0] += wgt * f0.x; acc[1] += wgt * f0.y;
                acc[2] += wgt * f1.x; acc[3] += wgt * f1.y;
                acc[4] += wgt * f2.x; acc[5] += wgt * f2.y;
                acc[6] += wgt * f3.x; acc[7] += wgt * f3.y;
                den += wgt;
            }
        }
        __syncwarp();
    }

    float inv = 1.f / (den + EPS);
    const float* bp = bias + lane * 8;
    float4 b0 = *(const float4*)bp;
    float4 b1 = *(const float4*)(bp + 4);
    float* op = out + (size_t)dst * CC + lane * 8;
    *(float4*)op = make_float4(acc[0] * inv + b0.x, acc[1] * inv + b0.y,
                               acc[2] * inv + b0.z, acc[3] * inv + b0.w);
    *(float4*)(op + 4) = make_float4(acc[4] * inv + b1.x, acc[5] * inv + b1.y,
                                     acc[6] * inv + b1.z, acc[7] * inv + b1.w);
}

// ---------------- launch ----------------
extern "C" void kernel_launch(void* const* d_in, const int* in_sizes, int n_in,
                              void* d_out, int out_size) {
    const float* x     = (const float*)d_in[0];
    const int*   ei    = (const int*)d_in[1];
    const float* W     = (const float*)d_in[2];
    const float* a_src = (const float*)d_in[3];
    const float* a_dst = (const float*)d_in[4];
    const float* bias  = (const float*)d_in[5];
    float*       out   = (float*)d_out;

    setup_kernel<<<(CC * FIN + 255) / 256, 256>>>(W);

    dim3 ggrid(CC / 128, (NN + 127) / 128);
    hgemm_kernel<<<ggrid, 256>>>(x, a_src, a_dst);

    hist_kernel<<<(EE / 4 + 255) / 256, 256>>>(ei);
    scan_kernel<<<1, 1024>>>();
    scatter_kernel<<<(EE / 4 + 255) / 256, 256>>>(ei);

    aggregate_kernel<<<(NN + AW - 1) / AW, 256>>>(bias, out);
}

// round 7
// speedup vs baseline: 4.1071x; 1.2387x over previous
#include <cuda_runtime.h>
#include <cuda_fp16.h>
#include <cstdint>

#define NN   40000
#define EE   640000
#define FIN  512
#define HH   8
#define FO   32
#define CC   256          // HH * FO
#define NEG_SLOPE 0.2f
#define EPS  1e-16f

#define NB   157          // scan blocks: ceil(40000/256)

// ---------------- scratch (global device arrays; no allocation) ----------------
__device__ __half g_hh[(size_t)NN * CC]; // projected features [N, H*F], fp16
__device__ __half g_Bh[CC * FIN];        // W repacked as [256 n][512 k], fp16
__device__ float  g_ssrc[NN * HH];
__device__ float  g_sdst[NN * HH];
__device__ int    g_cnt[NN];             // hist fills; scatter drains back to 0
__device__ int    g_off[NN + 1];
__device__ int    g_bsum[NB];
__device__ int    g_boff[NB];
__device__ int    g_csrc[EE];

__device__ __forceinline__ void mma_f16(float* c, const uint32_t* a, const uint32_t* b) {
    asm volatile(
        "mma.sync.aligned.m16n8k16.row.col.f32.f16.f16.f32 "
        "{%0,%1,%2,%3}, {%4,%5,%6,%7}, {%8,%9}, {%0,%1,%2,%3};"
        : "+f"(c[0]), "+f"(c[1]), "+f"(c[2]), "+f"(c[3])
        : "r"(a[0]), "r"(a[1]), "r"(a[2]), "r"(a[3]), "r"(b[0]), "r"(b[1]));
}

__device__ __forceinline__ void ldsm_x4(uint32_t* r, uint32_t addr) {
    asm volatile("ldmatrix.sync.aligned.m8n8.x4.shared.b16 {%0,%1,%2,%3}, [%4];"
        : "=r"(r[0]), "=r"(r[1]), "=r"(r[2]), "=r"(r[3]) : "r"(addr));
}

__device__ __forceinline__ uint2 f4_to_h8(float4 v) {
    __half2 h0 = __floats2half2_rn(v.x, v.y);
    __half2 h1 = __floats2half2_rn(v.z, v.w);
    uint2 u;
    u.x = *(uint32_t*)&h0;
    u.y = *(uint32_t*)&h1;
    return u;
}

// ---------------- setup: pack W -> Bh fp16 ----------------
__global__ void setup_kernel(const float* __restrict__ W) {
    int idx = blockIdx.x * blockDim.x + threadIdx.x;
    if (idx < CC * FIN) {
        int n = idx >> 9;          // 0..255 = head*32 + f
        int d = idx & 511;
        g_Bh[idx] = __float2half(W[(n >> 5) * (FIN * FO) + d * FO + (n & 31)]);
    }
}

// ---------------- fp16 tensor GEMM + fused s epilogue ----------------
// 128x128 tile, BK=32, 256 threads (8 warps), warp tile 64x32 via m16n8k16
__global__ __launch_bounds__(256) void hgemm_kernel(const float* __restrict__ A,
                                                    const float* __restrict__ a_src,
                                                    const float* __restrict__ a_dst) {
    __shared__ __half As[2][128][40];   // [m][k], 80B rows -> ldmatrix conflict-free
    __shared__ __half Bs[2][128][40];   // [n][k]
    __shared__ float  sh_as[CC], sh_ad[CC];

    int t    = threadIdx.x;
    int lane = t & 31, warp = t >> 5;
    int gid  = lane >> 2, tid4 = lane & 3;
    int wm   = (warp & 1) * 64;
    int wn   = (warp >> 1) * 32;
    int bm0  = blockIdx.y * 128;
    int bc0  = blockIdx.x * 128;

    sh_as[t] = a_src[t];
    sh_ad[t] = a_dst[t];

    uint32_t as_u32 = (uint32_t)__cvta_generic_to_shared(&As[0][0][0]);
    uint32_t bs_u32 = (uint32_t)__cvta_generic_to_shared(&Bs[0][0][0]);
    int ra   = wm + (lane & 15);
    int kaof = (lane >> 4) << 3;
    int rb   = wn + ((lane >> 4) << 3) + (lane & 7);
    int kbof = ((lane >> 3) & 1) << 3;

    float4 av[4];
    uint4  bv[2];

#pragma unroll
    for (int it = 0; it < 4; it++) {
        int i = t + it * 256, r = i >> 3, c4 = i & 7;
        int row = bm0 + r;
        av[it] = (row < NN) ? *(const float4*)(A + (size_t)row * FIN + c4 * 4)
                            : make_float4(0.f, 0.f, 0.f, 0.f);
    }
#pragma unroll
    for (int it = 0; it < 2; it++) {
        int i = t + it * 256, n = i >> 2, seg = i & 3;
        bv[it] = *(const uint4*)(g_Bh + (size_t)(bc0 + n) * FIN + seg * 8);
    }
#pragma unroll
    for (int it = 0; it < 4; it++) {
        int i = t + it * 256, r = i >> 3, c4 = i & 7;
        *(uint2*)&As[0][r][c4 * 4] = f4_to_h8(av[it]);
    }
#pragma unroll
    for (int it = 0; it < 2; it++) {
        int i = t + it * 256, n = i >> 2, seg = i & 3;
        *(uint4*)&Bs[0][n][seg * 8] = bv[it];
    }
    __syncthreads();

    float acc[16][4];
#pragma unroll
    for (int i = 0; i < 16; i++)
#pragma unroll
        for (int j = 0; j < 4; j++) acc[i][j] = 0.f;

#pragma unroll 1
    for (int c = 0; c < 16; c++) {
        int cur = c & 1;
        if (c < 15) {
            int k0 = (c + 1) * 32;
#pragma unroll
            for (int it = 0; it < 4; it++) {
                int i = t + it * 256, r = i >> 3, c4 = i & 7;
                int row = bm0 + r;
                av[it] = (row < NN) ? *(const float4*)(A + (size_t)row * FIN + k0 + c4 * 4)
                                    : make_float4(0.f, 0.f, 0.f, 0.f);
            }
#pragma unroll
            for (int it = 0; it < 2; it++) {
                int i = t + it * 256, n = i >> 2, seg = i & 3;
                bv[it] = *(const uint4*)(g_Bh + (size_t)(bc0 + n) * FIN + k0 + seg * 8);
            }
        }
        uint32_t abase = as_u32 + (uint32_t)cur * 10240;
        uint32_t bbase = bs_u32 + (uint32_t)cur * 10240;
#pragma unroll
        for (int ks = 0; ks < 2; ks++) {
            int kb = ks * 16;
            uint32_t af[4][4], bf[4][2];
#pragma unroll
            for (int mt = 0; mt < 4; mt++)
                ldsm_x4(af[mt], abase + (uint32_t)(((ra + mt * 16) * 40 + kb + kaof) * 2));
#pragma unroll
            for (int p = 0; p < 2; p++) {
                uint32_t tmp[4];
                ldsm_x4(tmp, bbase + (uint32_t)(((rb + p * 16) * 40 + kb + kbof) * 2));
                bf[2 * p][0]     = tmp[0];
                bf[2 * p][1]     = tmp[1];
                bf[2 * p + 1][0] = tmp[2];
                bf[2 * p + 1][1] = tmp[3];
            }
#pragma unroll
            for (int mt = 0; mt < 4; mt++)
#pragma unroll
                for (int nt = 0; nt < 4; nt++)
                    mma_f16(acc[mt * 4 + nt], af[mt], bf[nt]);
        }
        if (c < 15) {
            int nxt = cur ^ 1;
#pragma unroll
            for (int it = 0; it < 4; it++) {
                int i = t + it * 256, r = i >> 3, c4 = i & 7;
                *(uint2*)&As[nxt][r][c4 * 4] = f4_to_h8(av[it]);
            }
#pragma unroll
            for (int it = 0; it < 2; it++) {
                int i = t + it * 256, n = i >> 2, seg = i & 3;
                *(uint4*)&Bs[nxt][n][seg * 8] = bv[it];
            }
            __syncthreads();
        }
    }

    // ---- epilogue: store g_hh (fp16) + fused per-head s_src/s_dst dots ----
    int head = (bc0 + wn) >> 5;
#pragma unroll
    for (int mt = 0; mt < 4; mt++) {
        int row0 = bm0 + wm + mt * 16 + gid;
        float ps0 = 0.f, pd0 = 0.f, ps1 = 0.f, pd1 = 0.f;
#pragma unroll
        for (int nt = 0; nt < 4; nt++) {
            int col = bc0 + wn + nt * 8 + tid4 * 2;
            float* cc = acc[mt * 4 + nt];
            ps0 += cc[0] * sh_as[col] + cc[1] * sh_as[col + 1];
            pd0 += cc[0] * sh_ad[col] + cc[1] * sh_ad[col + 1];
            ps1 += cc[2] * sh_as[col] + cc[3] * sh_as[col + 1];
            pd1 += cc[2] * sh_ad[col] + cc[3] * sh_ad[col + 1];
            if (row0 < NN)
                *(__half2*)&g_hh[(size_t)row0 * CC + col] = __floats2half2_rn(cc[0], cc[1]);
            if (row0 + 8 < NN)
                *(__half2*)&g_hh[(size_t)(row0 + 8) * CC + col] = __floats2half2_rn(cc[2], cc[3]);
        }
        ps0 += __shfl_xor_sync(0xFFFFFFFF, ps0, 1);
        ps0 += __shfl_xor_sync(0xFFFFFFFF, ps0, 2);
        pd0 += __shfl_xor_sync(0xFFFFFFFF, pd0, 1);
        pd0 += __shfl_xor_sync(0xFFFFFFFF, pd0, 2);
        ps1 += __shfl_xor_sync(0xFFFFFFFF, ps1, 1);
        ps1 += __shfl_xor_sync(0xFFFFFFFF, ps1, 2);
        pd1 += __shfl_xor_sync(0xFFFFFFFF, pd1, 1);
        pd1 += __shfl_xor_sync(0xFFFFFFFF, pd1, 2);
        if (tid4 == 0) {
            if (row0 < NN) {
                g_ssrc[row0 * HH + head] = ps0;
                g_sdst[row0 * HH + head] = pd0;
            }
            if (row0 + 8 < NN) {
                g_ssrc[(row0 + 8) * HH + head] = ps1;
                g_sdst[(row0 + 8) * HH + head] = pd1;
            }
        }
    }
}

// ---------------- CSR build ----------------
__global__ void hist_kernel(const int* __restrict__ ei) {
    int q = blockIdx.x * blockDim.x + threadIdx.x;
    if (q < EE / 4) {
        int4 d = *(const int4*)(ei + EE + q * 4);
        atomicAdd(&g_cnt[d.x], 1);
        atomicAdd(&g_cnt[d.y], 1);
        atomicAdd(&g_cnt[d.z], 1);
        atomicAdd(&g_cnt[d.w], 1);
    }
}

// 3-phase parallel scan of g_cnt -> g_off (exclusive, g_off[0]=0)
__global__ void scan1_kernel() {
    __shared__ int sdata[256];
    int t = threadIdx.x, b = blockIdx.x;
    int i = b * 256 + t;
    int v = (i < NN) ? g_cnt[i] : 0;
    sdata[t] = v;
    __syncthreads();
#pragma unroll
    for (int d = 1; d < 256; d <<= 1) {
        int x = (t >= d) ? sdata[t - d] : 0;
        __syncthreads();
        sdata[t] += x;
        __syncthreads();
    }
    if (i < NN) g_off[i + 1] = sdata[t];      // block-local inclusive
    if (t == 255) g_bsum[b] = sdata[255];
}

__global__ void scan2_kernel() {
    __shared__ int sdata[256];
    int t = threadIdx.x;
    int v = (t < NB) ? g_bsum[t] : 0;
    sdata[t] = v;
    __syncthreads();
#pragma unroll
    for (int d = 1; d < 256; d <<= 1) {
        int x = (t >= d) ? sdata[t - d] : 0;
        __syncthreads();
        sdata[t] += x;
        __syncthreads();
    }
    if (t < NB) g_boff[t] = sdata[t] - v;     // exclusive block offset
}

__global__ void scan3_kernel() {
    int i = blockIdx.x * 256 + threadIdx.x;
    if (i < NN) g_off[i + 1] += g_boff[blockIdx.x];
    if (i == 0) g_off[0] = 0;
}

// scatter drains g_cnt back to 0 (keeps replay invariant; no g_ctr needed)
__global__ void scatter_kernel(const int* __restrict__ ei) {
    int q = blockIdx.x * blockDim.x + threadIdx.x;
    if (q < EE / 4) {
        int4 s = *(const int4*)(ei + q * 4);
        int4 d = *(const int4*)(ei + EE + q * 4);
        g_csrc[g_off[d.x] + atomicAdd(&g_cnt[d.x], -1) - 1] = s.x;
        g_csrc[g_off[d.y] + atomicAdd(&g_cnt[d.y], -1) - 1] = s.y;
        g_csrc[g_off[d.z] + atomicAdd(&g_cnt[d.z], -1) - 1] = s.z;
        g_csrc[g_off[d.w] + atomicAdd(&g_cnt[d.w], -1) - 1] = s.w;
    }
}

// ---------------- warp-per-dst softmax + aggregation (fp16 h, MLP-8) ----------------
#define AW 8
__global__ __launch_bounds__(256) void aggregate_kernel(const float* __restrict__ bias,
                                                        float* __restrict__ out) {
    __shared__ float sh_exp[AW][32][9];
    __shared__ int   sh_src[AW][32];

    int t = threadIdx.x, w = t >> 5, lane = t & 31;
    int dst = blockIdx.x * AW + w;
    if (dst >= NN) return;
    int hd = lane >> 2;

    int beg = g_off[dst];
    int deg = g_off[dst + 1] - beg;

    float4 sd0 = *(const float4*)&g_sdst[dst * HH];
    float4 sd1 = *(const float4*)&g_sdst[dst * HH + 4];

    float acc[8] = {0.f, 0.f, 0.f, 0.f, 0.f, 0.f, 0.f, 0.f};
    float den = 0.f;

#pragma unroll 1
    for (int c0 = 0; c0 < deg; c0 += 32) {
        int cl = min(32, deg - c0);
        if (lane < cl) {
            int s = g_csrc[beg + c0 + lane];
            sh_src[w][lane] = s;
            float4 v0 = *(const float4*)&g_ssrc[s * HH];
            float4 v1 = *(const float4*)&g_ssrc[s * HH + 4];
            float es[8] = {v0.x + sd0.x, v0.y + sd0.y, v0.z + sd0.z, v0.w + sd0.w,
                           v1.x + sd1.x, v1.y + sd1.y, v1.z + sd1.z, v1.w + sd1.w};
#pragma unroll
            for (int h = 0; h < HH; h++) {
                float e = es[h];
                e = (e >= 0.f) ? e : NEG_SLOPE * e;
                sh_exp[w][lane][h] = __expf(e);
            }
        }
        __syncwarp();
#pragma unroll 1
        for (int i = 0; i < cl; i += 8) {
            int   srcs[8];
            float wg[8];
#pragma unroll
            for (int j = 0; j < 8; j++) {
                int  ij = i + j;
                bool v  = ij < cl;
                int  si = v ? ij : 0;
                srcs[j] = sh_src[w][si];
                wg[j]   = v ? sh_exp[w][si][hd] : 0.f;
            }
            uint4 u[8];
#pragma unroll
            for (int j = 0; j < 8; j++)
                u[j] = *(const uint4*)(g_hh + (size_t)srcs[j] * CC + lane * 8);
#pragma unroll
            for (int j = 0; j < 8; j++) {
                __half2* hp = (__half2*)&u[j];
                float2 f0 = __half22float2(hp[0]);
                float2 f1 = __half22float2(hp[1]);
                float2 f2 = __half22float2(hp[2]);
                float2 f3 = __half22float2(hp[3]);
                float wgt = wg[j];
                acc[0] += wgt * f0.x; acc[1] += wgt * f0.y;
                acc[2] += wgt * f1.x; acc[3] += wgt * f1.y;
                acc[4] += wgt * f2.x; acc[5] += wgt * f2.y;
                acc[6] += wgt * f3.x; acc[7] += wgt * f3.y;
                den += wgt;
            }
        }
        __syncwarp();
    }

    float inv = 1.f / (den + EPS);
    const float* bp = bias + lane * 8;
    float4 b0 = *(const float4*)bp;
    float4 b1 = *(const float4*)(bp + 4);
    float* op = out + (size_t)dst * CC + lane * 8;
    *(float4*)op = make_float4(acc[0] * inv + b0.x, acc[1] * inv + b0.y,
                               acc[2] * inv + b0.z, acc[3] * inv + b0.w);
    *(float4*)(op + 4) = make_float4(acc[4] * inv + b1.x, acc[5] * inv + b1.y,
                                     acc[6] * inv + b1.z, acc[7] * inv + b1.w);
}

// ---------------- launch ----------------
extern "C" void kernel_launch(void* const* d_in, const int* in_sizes, int n_in,
                              void* d_out, int out_size) {
    const float* x     = (const float*)d_in[0];
    const int*   ei    = (const int*)d_in[1];
    const float* W     = (const float*)d_in[2];
    const float* a_src = (const float*)d_in[3];
    const float* a_dst = (const float*)d_in[4];
    const float* bias  = (const float*)d_in[5];
    float*       out   = (float*)d_out;

    setup_kernel<<<(CC * FIN + 255) / 256, 256>>>(W);

    dim3 ggrid(CC / 128, (NN + 127) / 128);
    hgemm_kernel<<<ggrid, 256>>>(x, a_src, a_dst);

    hist_kernel<<<(EE / 4 + 255) / 256, 256>>>(ei);
    scan1_kernel<<<NB, 256>>>();
    scan2_kernel<<<1, 256>>>();
    scan3_kernel<<<NB, 256>>>();
    scatter_kernel<<<(EE / 4 + 255) / 256, 256>>>(ei);

    aggregate_kernel<<<(NN + AW - 1) / AW, 256>>>(bias, out);
}